// round 1
// baseline (speedup 1.0000x reference)
#include <cuda_runtime.h>
#include <cstdint>

// Problem constants (fixed shapes for this dataset)
#define SDIM 9
#define FDIM 32
#define MAXN 16384
#define MAXE 524288

// ---------------- scratch (no allocations allowed) ----------------
__device__ int g_count[MAXN];
__device__ int g_off[MAXN + 1];
__device__ int g_cursor[MAXN];
__device__ int g_order[MAXE];

// ---------------- helpers ----------------
__device__ __forceinline__ float envelope_f(float d) {
    float u = __saturatef(d);
    float u2 = u * u;
    float u5 = u2 * u2 * u;
    // 1 - 21u^5 + 35u^6 - 15u^7
    return 1.0f + u5 * (-21.0f + u * (35.0f - 15.0f * u));
}

__device__ __forceinline__ unsigned long long pack2(float lo, float hi) {
    unsigned long long r;
    asm("mov.b64 %0, {%1, %2};" : "=l"(r) : "f"(lo), "f"(hi));
    return r;
}
__device__ __forceinline__ void unpack2(unsigned long long v, float& lo, float& hi) {
    asm("mov.b64 {%0, %1}, %2;" : "=f"(lo), "=f"(hi) : "l"(v));
}
// d = a * b + d   (packed 2x f32, Blackwell)
__device__ __forceinline__ void ffma2(unsigned long long& d,
                                      unsigned long long a,
                                      unsigned long long b) {
    asm("fma.rn.f32x2 %0, %1, %2, %0;" : "+l"(d) : "l"(a), "l"(b));
}

// ---------------- CSR build ----------------
__global__ void zero_kernel(int Nn) {
    int i = blockIdx.x * blockDim.x + threadIdx.x;
    if (i < Nn) g_count[i] = 0;
}

__global__ void hist_kernel(const int* __restrict__ ei, int E) {
    int e = blockIdx.x * blockDim.x + threadIdx.x;
    if (e < E) atomicAdd(&g_count[ei[E + e]], 1);  // dst = edge_index[1][e]
}

// single block, 1024 threads, exclusive scan of g_count -> g_off, init g_cursor
__global__ void scan_kernel(int Nn, int E) {
    __shared__ int wsum[32];
    const int PER = 16;
    int t = threadIdx.x;
    int base = t * PER;
    int c[PER];
    int tsum = 0;
#pragma unroll
    for (int k = 0; k < PER; k++) {
        int v = (base + k < Nn) ? g_count[base + k] : 0;
        c[k] = v;
        tsum += v;
    }
    int lane = t & 31, w = t >> 5;
    int v = tsum;
#pragma unroll
    for (int d = 1; d < 32; d <<= 1) {
        int o = __shfl_up_sync(0xffffffffu, v, d);
        if (lane >= d) v += o;
    }
    if (lane == 31) wsum[w] = v;
    __syncthreads();
    if (w == 0) {
        int s = wsum[lane];
#pragma unroll
        for (int d = 1; d < 32; d <<= 1) {
            int o = __shfl_up_sync(0xffffffffu, s, d);
            if (lane >= d) s += o;
        }
        wsum[lane] = s;  // inclusive warp sums
    }
    __syncthreads();
    int excl = v - tsum + ((w > 0) ? wsum[w - 1] : 0);
    int run = excl;
#pragma unroll
    for (int k = 0; k < PER; k++) {
        if (base + k < Nn) {
            g_off[base + k] = run;
            g_cursor[base + k] = run;
            run += c[k];
        }
    }
    if (t == 0) g_off[Nn] = E;
}

__global__ void scatter_kernel(const int* __restrict__ ei, int E) {
    int e = blockIdx.x * blockDim.x + threadIdx.x;
    if (e < E) {
        int d = ei[E + e];
        int pos = atomicAdd(&g_cursor[d], 1);
        g_order[pos] = e;
    }
}

// ---------------- main aggregation: one warp per destination node ----------------
// lane = channel f. Accumulators:
//   A[s]     = sum_e env(dist_e) * Y[e,s] * x[src,s,f]          (9 floats)
//   Z[q][r]  = sum_e env(Y[e,0]) * Y[e,r] * x[src,q,f]          (81 floats; r packed in f32x2 pairs)
// Epilogue:
//   out[n,p,f] = x[n,p,f] + Wsca[lp,f]*Wsph[lp,f]*A[p] + Wmix[lp,f]*sum_{q,r} cg[p,q,r]*Z[q][r]
__global__ __launch_bounds__(128, 3) void aggregate_kernel(
    const float* __restrict__ x, const int* __restrict__ ei,
    const float* __restrict__ ea, const float* __restrict__ Wsca,
    const float* __restrict__ Wsph, const float* __restrict__ Wmix,
    const float* __restrict__ cg, float* __restrict__ out, int Nn, int E) {
    // cg staged in shared, r-dim padded to 10 floats so every (p,q) row is 8B-aligned
    __shared__ __align__(16) float cgs[SDIM * SDIM * 10];
    int tid = threadIdx.x;
    for (int i = tid; i < SDIM * SDIM * 10; i += blockDim.x) {
        int r = i % 10;
        int pq = i / 10;
        cgs[i] = (r < 9) ? cg[pq * 9 + r] : 0.0f;
    }
    __syncthreads();

    int warp = tid >> 5;
    int lane = tid & 31;
    int n = blockIdx.x * (blockDim.x >> 5) + warp;
    if (n >= Nn) return;

    int beg = g_off[n];
    int end = g_off[n + 1];

    unsigned long long Z2[SDIM][4];  // r pairs (0,1)(2,3)(4,5)(6,7)
    float Z8[SDIM];                  // r = 8
    float A[SDIM];
#pragma unroll
    for (int q = 0; q < SDIM; q++) {
#pragma unroll
        for (int rp = 0; rp < 4; rp++) Z2[q][rp] = 0ull;
        Z8[q] = 0.0f;
        A[q] = 0.0f;
    }

    for (int i = beg; i < end; ++i) {
        int e = g_order[i];
        int src = ei[e];  // edge_index[0][e]
        const float* eap = ea + (size_t)e * (SDIM * 2);
        const float* xp = x + (size_t)src * (SDIM * FDIM) + lane;

        float xj[SDIM];
#pragma unroll
        for (int q = 0; q < SDIM; q++) xj[q] = xp[q * FDIM];

        float Y[SDIM];
#pragma unroll
        for (int s = 0; s < SDIM; s++) Y[s] = eap[2 * s];
        float dist = eap[1];

        float env_d = envelope_f(dist);
        float env_y = envelope_f(Y[0]);

        unsigned long long wr2[4];
#pragma unroll
        for (int rp = 0; rp < 4; rp++)
            wr2[rp] = pack2(env_y * Y[2 * rp], env_y * Y[2 * rp + 1]);
        float wr8 = env_y * Y[8];

#pragma unroll
        for (int q = 0; q < SDIM; q++) {
            unsigned long long xq2 = pack2(xj[q], xj[q]);
#pragma unroll
            for (int rp = 0; rp < 4; rp++) ffma2(Z2[q][rp], xq2, wr2[rp]);
            Z8[q] = fmaf(xj[q], wr8, Z8[q]);
            A[q] = fmaf(env_d * Y[q], xj[q], A[q]);
        }
    }

    // epilogue: contract Z with cg, apply weights, add residual
#pragma unroll
    for (int p = 0; p < SDIM; p++) {
        unsigned long long acc2 = 0ull;
        float accs = 0.0f;
#pragma unroll
        for (int q = 0; q < SDIM; q++) {
            const float* cr = &cgs[p * 90 + q * 10];
            const unsigned long long* cr2 = (const unsigned long long*)cr;
#pragma unroll
            for (int rp = 0; rp < 4; rp++) ffma2(acc2, cr2[rp], Z2[q][rp]);
            accs = fmaf(cr[8], Z8[q], accs);
        }
        float lo, hi;
        unpack2(acc2, lo, hi);
        float mixed = lo + hi + accs;

        int lp = (p == 0) ? 0 : ((p < 4) ? 1 : 2);
        float wa = Wsca[lp * FDIM + lane] * Wsph[lp * FDIM + lane];
        float wm = Wmix[lp * FDIM + lane];
        size_t o = (size_t)n * (SDIM * FDIM) + p * FDIM + lane;
        out[o] = x[o] + wa * A[p] + wm * mixed;
    }
}

// ---------------- launch ----------------
extern "C" void kernel_launch(void* const* d_in, const int* in_sizes, int n_in,
                              void* d_out, int out_size) {
    const float* x    = (const float*)d_in[0];
    const int*   ei   = (const int*)d_in[1];
    const float* ea   = (const float*)d_in[2];
    const float* Wsca = (const float*)d_in[3];
    const float* Wsph = (const float*)d_in[4];
    const float* Wmix = (const float*)d_in[5];
    const float* cg   = (const float*)d_in[6];
    float* out = (float*)d_out;

    int E  = in_sizes[1] / 2;
    int Nn = in_sizes[0] / (SDIM * FDIM);

    zero_kernel<<<(Nn + 255) / 256, 256>>>(Nn);
    hist_kernel<<<(E + 255) / 256, 256>>>(ei, E);
    scan_kernel<<<1, 1024>>>(Nn, E);
    scatter_kernel<<<(E + 255) / 256, 256>>>(ei, E);

    int warps_per_block = 4;  // 128 threads
    int blocks = (Nn + warps_per_block - 1) / warps_per_block;
    aggregate_kernel<<<blocks, 128>>>(x, ei, ea, Wsca, Wsph, Wmix, cg, out, Nn, E);
}

// round 3
// speedup vs baseline: 1.1520x; 1.1520x over previous
#include <cuda_runtime.h>
#include <cstdint>

// Problem constants (fixed shapes for this dataset)
#define SDIM 9
#define FDIM 32
#define MAXN 16384
#define MAXE 524288

// ---------------- scratch (no allocations allowed) ----------------
__device__ int g_count[MAXN];
__device__ int g_off[MAXN + 1];
__device__ int g_cursor[MAXN];
// dst-sorted edge records: 5 float4 per edge:
//   rec[0] = (src_bits, wr8, wa8, unused)
//   rec[1] = (wr0, wr1, wr2, wr3)      wr[r] = env(Y0) * Y[r]
//   rec[2] = (wr4, wr5, wr6, wr7)
//   rec[3] = (wa0, wa1, wa2, wa3)      wa[s] = env(dist) * Y[s]
//   rec[4] = (wa4, wa5, wa6, wa7)
__device__ float4 g_rec[(size_t)MAXE * 5];

// ---------------- helpers ----------------
__device__ __forceinline__ float envelope_f(float d) {
    float u = __saturatef(d);
    float u2 = u * u;
    float u5 = u2 * u2 * u;
    // 1 - 21u^5 + 35u^6 - 15u^7
    return 1.0f + u5 * (-21.0f + u * (35.0f - 15.0f * u));
}

__device__ __forceinline__ unsigned long long pack2(float lo, float hi) {
    unsigned long long r;
    asm("mov.b64 %0, {%1, %2};" : "=l"(r) : "f"(lo), "f"(hi));
    return r;
}
__device__ __forceinline__ void unpack2(unsigned long long v, float& lo, float& hi) {
    asm("mov.b64 {%0, %1}, %2;" : "=f"(lo), "=f"(hi) : "l"(v));
}
// d = a * b + d   (packed 2x f32, Blackwell)
__device__ __forceinline__ void ffma2(unsigned long long& d,
                                      unsigned long long a,
                                      unsigned long long b) {
    asm("fma.rn.f32x2 %0, %1, %2, %0;" : "+l"(d) : "l"(a), "l"(b));
}

// ---------------- CSR build ----------------
__global__ void zero_kernel(int Nn) {
    int i = blockIdx.x * blockDim.x + threadIdx.x;
    if (i < Nn) g_count[i] = 0;
}

__global__ void hist_kernel(const int* __restrict__ ei, int E) {
    int e = blockIdx.x * blockDim.x + threadIdx.x;
    if (e < E) atomicAdd(&g_count[ei[E + e]], 1);  // dst = edge_index[1][e]
}

// single block, 1024 threads, exclusive scan of g_count -> g_off, init g_cursor
__global__ void scan_kernel(int Nn, int E) {
    __shared__ int wsum[32];
    const int PER = 16;
    int t = threadIdx.x;
    int base = t * PER;
    int c[PER];
    int tsum = 0;
#pragma unroll
    for (int k = 0; k < PER; k++) {
        int v = (base + k < Nn) ? g_count[base + k] : 0;
        c[k] = v;
        tsum += v;
    }
    int lane = t & 31, w = t >> 5;
    int v = tsum;
#pragma unroll
    for (int d = 1; d < 32; d <<= 1) {
        int o = __shfl_up_sync(0xffffffffu, v, d);
        if (lane >= d) v += o;
    }
    if (lane == 31) wsum[w] = v;
    __syncthreads();
    if (w == 0) {
        int s = wsum[lane];
#pragma unroll
        for (int d = 1; d < 32; d <<= 1) {
            int o = __shfl_up_sync(0xffffffffu, s, d);
            if (lane >= d) s += o;
        }
        wsum[lane] = s;  // inclusive warp sums
    }
    __syncthreads();
    int excl = v - tsum + ((w > 0) ? wsum[w - 1] : 0);
    int run = excl;
#pragma unroll
    for (int k = 0; k < PER; k++) {
        if (base + k < Nn) {
            g_off[base + k] = run;
            g_cursor[base + k] = run;
            run += c[k];
        }
    }
    if (t == 0) g_off[Nn] = E;
}

// fused scatter + per-edge scalar precompute: writes dst-sorted records
__global__ void build_records(const int* __restrict__ ei,
                              const float* __restrict__ ea, int E) {
    int e = blockIdx.x * blockDim.x + threadIdx.x;
    if (e >= E) return;
    int src = ei[e];
    int dst = ei[E + e];

    // ea layout: [e][s][2] = (Y_s, dist); stride 18 floats, 8B aligned
    const float2* p = (const float2*)(ea + (size_t)e * (SDIM * 2));
    float Y[SDIM];
    float dist;
    {
        float2 v0 = p[0];
        Y[0] = v0.x;
        dist = v0.y;
#pragma unroll
        for (int s = 1; s < SDIM; s++) Y[s] = p[s].x;
    }
    float env_d = envelope_f(dist);
    float env_y = envelope_f(Y[0]);

    int pos = atomicAdd(&g_cursor[dst], 1);
    float4* rec = g_rec + (size_t)pos * 5;
    rec[0] = make_float4(__int_as_float(src), env_y * Y[8], env_d * Y[8], 0.0f);
    rec[1] = make_float4(env_y * Y[0], env_y * Y[1], env_y * Y[2], env_y * Y[3]);
    rec[2] = make_float4(env_y * Y[4], env_y * Y[5], env_y * Y[6], env_y * Y[7]);
    rec[3] = make_float4(env_d * Y[0], env_d * Y[1], env_d * Y[2], env_d * Y[3]);
    rec[4] = make_float4(env_d * Y[4], env_d * Y[5], env_d * Y[6], env_d * Y[7]);
}

// ---------------- main aggregation: one warp per destination node ----------------
// lane = channel f. Accumulators:
//   A[s]     = sum_e wa[s] * x[src,s,f]                  (9 floats)
//   Z[q][r]  = sum_e wr[r] * x[src,q,f]                  (81 floats; r packed in f32x2 pairs)
// Epilogue:
//   out[n,p,f] = x[n,p,f] + Wsca*Wsph*A[p] + Wmix*sum_{q,r} cg[p,q,r]*Z[q][r]
__global__ __launch_bounds__(128, 3) void aggregate_kernel(
    const float* __restrict__ x, const float* __restrict__ Wsca,
    const float* __restrict__ Wsph, const float* __restrict__ Wmix,
    const float* __restrict__ cg, float* __restrict__ out, int Nn) {
    // cg staged in shared, r-dim padded to 10 floats so every (p,q) row is 8B-aligned
    __shared__ __align__(16) float cgs[SDIM * SDIM * 10];
    int tid = threadIdx.x;
    for (int i = tid; i < SDIM * SDIM * 10; i += blockDim.x) {
        int r = i % 10;
        int pq = i / 10;
        cgs[i] = (r < 9) ? cg[pq * 9 + r] : 0.0f;
    }
    __syncthreads();

    int warp = tid >> 5;
    int lane = tid & 31;
    int n = blockIdx.x * (blockDim.x >> 5) + warp;
    if (n >= Nn) return;

    int beg = g_off[n];
    int end = g_off[n + 1];

    unsigned long long Z2[SDIM][4];  // r pairs (0,1)(2,3)(4,5)(6,7)
    float Z8[SDIM];                  // r = 8
    float A[SDIM];
#pragma unroll
    for (int q = 0; q < SDIM; q++) {
#pragma unroll
        for (int rp = 0; rp < 4; rp++) Z2[q][rp] = 0ull;
        Z8[q] = 0.0f;
        A[q] = 0.0f;
    }

#pragma unroll 2
    for (int i = beg; i < end; ++i) {
        const float4* rec = g_rec + (size_t)i * 5;
        float4 r0 = __ldg(rec + 0);
        float4 r1 = __ldg(rec + 1);
        float4 r2 = __ldg(rec + 2);
        float4 r3 = __ldg(rec + 3);
        float4 r4 = __ldg(rec + 4);

        int src = __float_as_int(r0.x);
        const float* xp = x + (size_t)src * (SDIM * FDIM) + lane;
        float xj[SDIM];
#pragma unroll
        for (int q = 0; q < SDIM; q++) xj[q] = __ldg(xp + q * FDIM);

        unsigned long long wr2[4];
        wr2[0] = pack2(r1.x, r1.y);
        wr2[1] = pack2(r1.z, r1.w);
        wr2[2] = pack2(r2.x, r2.y);
        wr2[3] = pack2(r2.z, r2.w);
        float wr8 = r0.y;
        float wa[SDIM] = {r3.x, r3.y, r3.z, r3.w, r4.x, r4.y, r4.z, r4.w, r0.z};

#pragma unroll
        for (int q = 0; q < SDIM; q++) {
            unsigned long long xq2 = pack2(xj[q], xj[q]);
#pragma unroll
            for (int rp = 0; rp < 4; rp++) ffma2(Z2[q][rp], xq2, wr2[rp]);
            Z8[q] = fmaf(xj[q], wr8, Z8[q]);
            A[q] = fmaf(wa[q], xj[q], A[q]);
        }
    }

    // epilogue: contract Z with cg, apply weights, add residual
#pragma unroll
    for (int p = 0; p < SDIM; p++) {
        unsigned long long acc2 = 0ull;
        float accs = 0.0f;
#pragma unroll
        for (int q = 0; q < SDIM; q++) {
            const float* cr = &cgs[p * 90 + q * 10];
            const unsigned long long* cr2 = (const unsigned long long*)cr;
#pragma unroll
            for (int rp = 0; rp < 4; rp++) ffma2(acc2, cr2[rp], Z2[q][rp]);
            accs = fmaf(cr[8], Z8[q], accs);
        }
        float lo, hi;
        unpack2(acc2, lo, hi);
        float mixed = lo + hi + accs;

        int lp = (p == 0) ? 0 : ((p < 4) ? 1 : 2);
        float wa_ = Wsca[lp * FDIM + lane] * Wsph[lp * FDIM + lane];
        float wm = Wmix[lp * FDIM + lane];
        size_t o = (size_t)n * (SDIM * FDIM) + p * FDIM + lane;
        out[o] = x[o] + wa_ * A[p] + wm * mixed;
    }
}

// ---------------- launch ----------------
extern "C" void kernel_launch(void* const* d_in, const int* in_sizes, int n_in,
                              void* d_out, int out_size) {
    const float* x    = (const float*)d_in[0];
    const int*   ei   = (const int*)d_in[1];
    const float* ea   = (const float*)d_in[2];
    const float* Wsca = (const float*)d_in[3];
    const float* Wsph = (const float*)d_in[4];
    const float* Wmix = (const float*)d_in[5];
    const float* cg   = (const float*)d_in[6];
    float* out = (float*)d_out;

    int E  = in_sizes[1] / 2;
    int Nn = in_sizes[0] / (SDIM * FDIM);

    zero_kernel<<<(Nn + 255) / 256, 256>>>(Nn);
    hist_kernel<<<(E + 255) / 256, 256>>>(ei, E);
    scan_kernel<<<1, 1024>>>(Nn, E);
    build_records<<<(E + 255) / 256, 256>>>(ei, ea, E);

    int warps_per_block = 4;  // 128 threads
    int blocks = (Nn + warps_per_block - 1) / warps_per_block;
    aggregate_kernel<<<blocks, 128>>>(x, Wsca, Wsph, Wmix, cg, out, Nn);
}